// round 17
// baseline (speedup 1.0000x reference)
#include <cuda_runtime.h>
#include <cuda_bf16.h>
#include <math.h>
#include <stdint.h>

// Problem constants
#define BB   4
#define SS   2048
#define DD   1024
#define HH   16
#define DH   64
#define KTOP 409        // max(S // 5, 1)

// ---------------- scratch (device globals; no allocation allowed) ----------------
__device__ float   g_Qt[(size_t)BB * DD * SS];   // Q transposed: [b*D + j][s]
__device__ float   g_Kt[(size_t)BB * DD * SS];   // K transposed
__device__ float2  g_P[(size_t)BB * DD * SS];    // spectrum product, REV-SLOT order
__device__ float2  g_Ps[64 * SS];                // d-reduced spectra, REV-SLOT order
__device__ float2  g_wk[64 * 512];               // (weight, index) per (b,h)
__device__ float   g_zv[64 * DD];                // weighted xv sums per (b,h)
__device__ float   g_att[BB * DD];
__device__ float   g_y[BB * DD];
__device__ float2  g_twf[1024];                  // exp(-2*pi*i*j/2048)

// bf16 hi/lo pre-split operands
__device__ __nv_bfloat16 g_Ahq[(size_t)DD * DD], g_Alq[(size_t)DD * DD];
__device__ __nv_bfloat16 g_Ahk[(size_t)DD * DD], g_Alk[(size_t)DD * DD];
__device__ __nv_bfloat16 g_Bhq[(size_t)BB * SS * DD], g_Blq[(size_t)BB * SS * DD];
__device__ __nv_bfloat16 g_Bhk[(size_t)BB * SS * DD], g_Blk[(size_t)BB * SS * DD];

// ---------------- PTX helpers (sm_80-compatible subset only) ----------------
__device__ __forceinline__ uint32_t smem_u32(const void* p) {
    uint32_t a;
    asm("{ .reg .u64 t; cvta.to.shared.u64 t, %1; cvt.u32.u64 %0, t; }" : "=r"(a) : "l"(p));
    return a;
}
__device__ __forceinline__ void ldsm_x4(uint32_t (&r)[4], uint32_t addr) {
    asm volatile("ldmatrix.sync.aligned.m8n8.x4.shared.b16 {%0,%1,%2,%3}, [%4];"
        : "=r"(r[0]), "=r"(r[1]), "=r"(r[2]), "=r"(r[3]) : "r"(addr));
}
__device__ __forceinline__ void mma_bf16(float (&c)[4], const uint32_t (&a)[4],
                                         uint32_t b0, uint32_t b1) {
    asm volatile(
        "mma.sync.aligned.m16n8k16.row.col.f32.bf16.bf16.f32 "
        "{%0,%1,%2,%3}, {%4,%5,%6,%7}, {%8,%9}, {%0,%1,%2,%3};"
        : "+f"(c[0]), "+f"(c[1]), "+f"(c[2]), "+f"(c[3])
        : "r"(a[0]), "r"(a[1]), "r"(a[2]), "r"(a[3]), "r"(b0), "r"(b1));
}
__device__ __forceinline__ void cp16(uint32_t dst, const void* src) {
    asm volatile("cp.async.cg.shared.global [%0], [%1], 16;" :: "r"(dst), "l"(src));
}
#define CP_COMMIT() asm volatile("cp.async.commit_group;" ::: "memory")
#define CP_WAIT1()  asm volatile("cp.async.wait_group 1;" ::: "memory")
#define CP_WAIT0()  asm volatile("cp.async.wait_group 0;" ::: "memory")

// ---------------- FFT helpers ----------------
__device__ __forceinline__ void bflyDIT(float2& u, float2& v, float2 w) {
    float tr = w.x * v.x - w.y * v.y;
    float ti = w.x * v.y + w.y * v.x;
    float2 t = make_float2(u.x - tr, u.y - ti);
    u = make_float2(u.x + tr, u.y + ti);
    v = t;
}
__device__ __forceinline__ void bflyDIF(float2& u, float2& v, float2 w) {
    float2 t = make_float2(u.x - v.x, u.y - v.y);
    u = make_float2(u.x + v.x, u.y + v.y);
    v = make_float2(t.x * w.x - t.y * w.y, t.x * w.y + t.y * w.x);
}

// DIT FFT, bit-reversed input in z, natural output.
// Stages half=1..128 in smem; last 3 (256/512/1024) in regs: r[k] = Z[tid+256k].
__device__ void fft2048_dit_hybrid(float2* z, const float2* tw, float2 (&r)[8]) {
    int tid = threadIdx.x;
    for (int half = 1; half < 256; half <<= 1) {
        int step = 1024 / half;
        for (int jj = tid; jj < 1024; jj += 256) {
            int p  = jj & (half - 1);
            int i0 = ((jj ^ p) << 1) | p;
            int i1 = i0 + half;
            float2 w = tw[p * step];
            float2 v = z[i1];
            float tr = w.x * v.x - w.y * v.y;
            float ti = w.x * v.y + w.y * v.x;
            float2 u = z[i0];
            z[i0] = make_float2(u.x + tr, u.y + ti);
            z[i1] = make_float2(u.x - tr, u.y - ti);
        }
        __syncthreads();
    }
#pragma unroll
    for (int k = 0; k < 8; k++) r[k] = z[tid + 256 * k];
    float2 w4 = tw[4 * tid];
    bflyDIT(r[0], r[1], w4); bflyDIT(r[2], r[3], w4);
    bflyDIT(r[4], r[5], w4); bflyDIT(r[6], r[7], w4);
    float2 w20 = tw[2 * tid], w21 = tw[2 * tid + 512];
    bflyDIT(r[0], r[2], w20); bflyDIT(r[1], r[3], w21);
    bflyDIT(r[4], r[6], w20); bflyDIT(r[5], r[7], w21);
    bflyDIT(r[0], r[4], tw[tid]);
    bflyDIT(r[1], r[5], tw[tid + 256]);
    bflyDIT(r[2], r[6], tw[tid + 512]);
    bflyDIT(r[3], r[7], tw[tid + 768]);
}

__device__ __forceinline__ unsigned int fenc(float v) {
    unsigned int u = __float_as_uint(v);
    return (u & 0x80000000u) ? ~u : (u | 0x80000000u);
}
__device__ __forceinline__ float fdec(unsigned int e) {
    unsigned int u = (e & 0x80000000u) ? (e & 0x7FFFFFFFu) : ~e;
    return __uint_as_float(u);
}

// ---------------- kernel 0: twiddle table ----------------
__global__ void tw_init_kernel() {
    int i = blockIdx.x * blockDim.x + threadIdx.x;
    if (i < 1024) {
        double ang = -2.0 * 3.14159265358979323846 * (double)i / 2048.0;
        g_twf[i] = make_float2((float)cos(ang), (float)sin(ang));
    }
}

// ---------------- kernel 0b: W transpose + bf16 hi/lo split ----------------
__global__ void splitw_kernel(const float* __restrict__ W,
                              __nv_bfloat16* __restrict__ Ah,
                              __nv_bfloat16* __restrict__ Al) {
    __shared__ float t[32][33];
    int bx = blockIdx.x * 32, by = blockIdx.y * 32;
    int x = threadIdx.x, y = threadIdx.y;  // block (32,8)
#pragma unroll
    for (int i = 0; i < 32; i += 8)
        t[y + i][x] = W[(size_t)(by + y + i) * DD + bx + x];
    __syncthreads();
#pragma unroll
    for (int i = 0; i < 32; i += 8) {
        float v = t[x][y + i];
        __nv_bfloat16 h = __float2bfloat16(v);
        __nv_bfloat16 l = __float2bfloat16(v - __bfloat162float(h));
        Ah[(size_t)(bx + y + i) * DD + by + x] = h;
        Al[(size_t)(bx + y + i) * DD + by + x] = l;
    }
}

// ---------------- kernel 0c: X bf16 hi/lo split (elementwise) ----------------
__global__ void splitx_kernel(const float* __restrict__ X,
                              __nv_bfloat16* __restrict__ H,
                              __nv_bfloat16* __restrict__ L) {
    size_t i = ((size_t)blockIdx.x * 256 + threadIdx.x) * 4;
    float4 v = *(const float4*)&X[i];
    __nv_bfloat162 h0 = __float22bfloat162_rn(make_float2(v.x, v.y));
    __nv_bfloat162 h1 = __float22bfloat162_rn(make_float2(v.z, v.w));
    float2 f0 = __bfloat1622float2(h0), f1 = __bfloat1622float2(h1);
    __nv_bfloat162 l0 = __float22bfloat162_rn(make_float2(v.x - f0.x, v.y - f0.y));
    __nv_bfloat162 l1 = __float22bfloat162_rn(make_float2(v.z - f1.x, v.w - f1.y));
    uint2 Hv, Lv;
    Hv.x = *(uint32_t*)&h0; Hv.y = *(uint32_t*)&h1;
    Lv.x = *(uint32_t*)&l0; Lv.y = *(uint32_t*)&l1;
    *(uint2*)&H[i] = Hv;
    *(uint2*)&L[i] = Lv;
}

// ---------------- kernel 1: bf16x3 tensor-core GEMM, 128x256 tile ----------------
// Ct[(b*D + j)*S + s] = sum_c A[j][c] * B[(b*S+s)][c] + bias[j]
// Both GEMMs in one launch; which = blockIdx.z >> 2.
#define ROWB   48
#define A_T    (128 * ROWB)              // 6144 B
#define B_T    (256 * ROWB)              // 12288 B
#define STG    (2 * A_T + 2 * B_T)       // 36864 B (Ah, Al, Bh, Bl)
#define PIPE   3
#define GSMEM  (PIPE * STG)              // 110592 B

__global__ __launch_bounds__(256, 1)
void gemm_mma_kernel(const float* __restrict__ bq, const float* __restrict__ bk) {
    extern __shared__ __align__(16) char sm[];

    const int tid  = threadIdx.x;
    const int lane = tid & 31, wid = tid >> 5;
    const int mw = wid & 3, nw = wid >> 2;           // 4 x 2 warp grid; warptile 32x128
    const int which = blockIdx.z >> 2;
    const int b  = blockIdx.z & 3;
    const int j0 = blockIdx.x * 128;
    const int s0 = blockIdx.y * 256;

    const __nv_bfloat16* Ah = which ? g_Ahk : g_Ahq;
    const __nv_bfloat16* Al = which ? g_Alk : g_Alq;
    const __nv_bfloat16* Bh = which ? g_Bhk : g_Bhq;
    const __nv_bfloat16* Bl = which ? g_Blk : g_Blq;
    const float* bias = which ? bk : bq;
    float* Ct = which ? g_Kt : g_Qt;

    // ---- cp.async mapping ----
    // A: thread -> (row = tid>>1, half = tid&1): 1 chunk each for Ah, Al
    // B: thread -> row = tid: 2 chunks (half 0,1) each for Bh, Bl
    const int arow = tid >> 1, ahalf = tid & 1;
    const uint32_t dA = arow * ROWB + ahalf * 16;
    const __nv_bfloat16* sAh = Ah + (size_t)(j0 + arow) * DD + ahalf * 8;
    const __nv_bfloat16* sAl = Al + (size_t)(j0 + arow) * DD + ahalf * 8;
    const uint32_t dB = tid * ROWB;
    const __nv_bfloat16* sBh = Bh + (size_t)(b * SS + s0 + tid) * DD;
    const __nv_bfloat16* sBl = Bl + (size_t)(b * SS + s0 + tid) * DD;

    uint32_t smb = smem_u32(sm);

    // ---- ldmatrix lane addressing ----
    const int aoff = (lane & 15) * ROWB + (lane >> 4) * 16;
    const int am0 = (mw * 32 +  0) * ROWB + aoff;
    const int am1 = (mw * 32 + 16) * ROWB + aoff;
    const int nloc = (lane & 7) + ((lane >> 4) << 3);
    const int boff = ((lane >> 3) & 1) * 16;
    int bn[8];
#pragma unroll
    for (int nf = 0; nf < 8; nf++)
        bn[nf] = (nw * 128 + nf * 16 + nloc) * ROWB + boff;

    float acc[2][16][4];
#pragma unroll
    for (int mi = 0; mi < 2; mi++)
#pragma unroll
        for (int ni = 0; ni < 16; ni++)
#pragma unroll
            for (int q = 0; q < 4; q++) acc[mi][ni][q] = 0.0f;

#define ISSUE(st) do {                                                  \
        uint32_t d = smb + ((st) % PIPE) * STG;                         \
        int kt = (st) * 16;                                             \
        cp16(d + dA,                   sAh + kt);                       \
        cp16(d + A_T + dA,             sAl + kt);                       \
        cp16(d + 2 * A_T + dB,         sBh + kt);                       \
        cp16(d + 2 * A_T + dB + 16,    sBh + kt + 8);                   \
        cp16(d + 2 * A_T + B_T + dB,      sBl + kt);                    \
        cp16(d + 2 * A_T + B_T + dB + 16, sBl + kt + 8);                \
        CP_COMMIT();                                                    \
    } while (0)

    ISSUE(0); ISSUE(1);

    const int NST = DD / 16;   // 64 stages
    for (int s = 0; s < NST; s++) {
        if (s + 2 < NST) CP_WAIT1(); else CP_WAIT0();
        __syncthreads();
        if (s + 2 < NST) ISSUE(s + 2);

        uint32_t base = smb + (s % PIPE) * STG;
        uint32_t a0h[4], a1h[4], a0l[4], a1l[4];
        ldsm_x4(a0h, base + am0);
        ldsm_x4(a1h, base + am1);
        ldsm_x4(a0l, base + A_T + am0);
        ldsm_x4(a1l, base + A_T + am1);
#pragma unroll
        for (int nf = 0; nf < 8; nf++) {
            uint32_t bhf[4], blf[4];
            ldsm_x4(bhf, base + 2 * A_T + bn[nf]);
            ldsm_x4(blf, base + 2 * A_T + B_T + bn[nf]);
            mma_bf16(acc[0][2 * nf],     a0h, bhf[0], bhf[1]);
            mma_bf16(acc[0][2 * nf + 1], a0h, bhf[2], bhf[3]);
            mma_bf16(acc[1][2 * nf],     a1h, bhf[0], bhf[1]);
            mma_bf16(acc[1][2 * nf + 1], a1h, bhf[2], bhf[3]);
            mma_bf16(acc[0][2 * nf],     a0h, blf[0], blf[1]);
            mma_bf16(acc[0][2 * nf + 1], a0h, blf[2], blf[3]);
            mma_bf16(acc[1][2 * nf],     a1h, blf[0], blf[1]);
            mma_bf16(acc[1][2 * nf + 1], a1h, blf[2], blf[3]);
            mma_bf16(acc[0][2 * nf],     a0l, bhf[0], bhf[1]);
            mma_bf16(acc[0][2 * nf + 1], a0l, bhf[2], bhf[3]);
            mma_bf16(acc[1][2 * nf],     a1l, bhf[0], bhf[1]);
            mma_bf16(acc[1][2 * nf + 1], a1l, bhf[2], bhf[3]);
        }
    }
#undef ISSUE

    const int grp = lane >> 2, qd = lane & 3;
#pragma unroll
    for (int mi = 0; mi < 2; mi++) {
#pragma unroll
        for (int half = 0; half < 2; half++) {
            int j = j0 + mw * 32 + mi * 16 + grp + half * 8;
            float bj = bias[j];
            float* dst = Ct + ((size_t)(b * DD + j)) * SS + s0 + nw * 128 + qd * 2;
#pragma unroll
            for (int ni = 0; ni < 16; ni++) {
                float2 v = make_float2(acc[mi][ni][half * 2 + 0] + bj,
                                       acc[mi][ni][half * 2 + 1] + bj);
                *(float2*)(dst + ni * 8) = v;
            }
        }
    }
}

// ---------------- kernel 2: packed forward DIF FFT of (q + i*k) ----------------
__global__ void fft_qk_kernel() {
    int bhd = blockIdx.x;
    const float* qr = g_Qt + (size_t)bhd * SS;
    const float* kr = g_Kt + (size_t)bhd * SS;

    __shared__ float2 z[2048];
    __shared__ float2 tw[1024];

    int tid = threadIdx.x;
    for (int i = tid; i < 1024; i += 256) tw[i] = g_twf[i];

    float2 r[8];
#pragma unroll
    for (int k = 0; k < 8; k++) {
        int s = tid + 256 * k;
        r[k] = make_float2(qr[s], kr[s]);
    }
    __syncthreads();   // tw visible

    // DIF reg stages: half = 1024, 512, 256
#pragma unroll
    for (int k = 0; k < 4; k++) bflyDIF(r[k], r[k + 4], tw[tid + 256 * k]);
    {
        float2 w0 = tw[2 * tid], w1 = tw[2 * tid + 512];
        bflyDIF(r[0], r[2], w0); bflyDIF(r[1], r[3], w1);
        bflyDIF(r[4], r[6], w0); bflyDIF(r[5], r[7], w1);
    }
    {
        float2 w = tw[4 * tid];
        bflyDIF(r[0], r[1], w); bflyDIF(r[2], r[3], w);
        bflyDIF(r[4], r[5], w); bflyDIF(r[6], r[7], w);
    }
#pragma unroll
    for (int k = 0; k < 8; k++) z[tid + 256 * k] = r[k];
    __syncthreads();

    // DIF smem stages: half = 128 .. 1
    for (int half = 128; half >= 1; half >>= 1) {
        int step = 1024 / half;
        for (int jj = tid; jj < 1024; jj += 256) {
            int p  = jj & (half - 1);
            int i0 = ((jj ^ p) << 1) | p;
            int i1 = i0 + half;
            float2 w = tw[p * step];
            float2 u = z[i0], v = z[i1];
            float2 t = make_float2(u.x - v.x, u.y - v.y);
            z[i0] = make_float2(u.x + v.x, u.y + v.y);
            z[i1] = make_float2(t.x * w.x - t.y * w.y, t.x * w.y + t.y * w.x);
        }
        __syncthreads();
    }

    // Unpack in rev domain: slot i holds Z[brev(i)].  P = Q * conj(K).
#pragma unroll
    for (int k = 0; k < 8; k++) {
        int i = tid + 256 * k;
        int f  = __brev((unsigned)i) >> 21;
        int fp = (2048 - f) & 2047;
        int jp = __brev((unsigned)fp) >> 21;
        float2 Zf = z[i];
        float2 Zc = z[jp];
        float Qr =  0.5f * (Zf.x + Zc.x);
        float Qi =  0.5f * (Zf.y - Zc.y);
        float Kr =  0.5f * (Zf.y + Zc.y);
        float Ki = -0.5f * (Zf.x - Zc.x);
        g_P[(size_t)bhd * SS + i] = make_float2(Qr * Kr + Qi * Ki, Qi * Kr - Qr * Ki);
    }
}

// ---------------- kernel 2b: reduce spectra over channel dim d ----------------
__global__ void reduce_kernel() {
    int bh = blockIdx.x;
    int f  = blockIdx.y * 256 + threadIdx.x;
    const float2* Pb = g_P + (size_t)bh * DH * SS + f;
    float sr = 0.0f, si = 0.0f;
#pragma unroll 8
    for (int d = 0; d < DH; d++) {
        float2 p = Pb[(size_t)d * SS];
        sr += p.x;
        si += p.y;
    }
    g_Ps[bh * SS + f] = make_float2(sr, si);
}

// ---------------- kernel 3: inverse DIT FFT + exact radix-select top-k + softmax ---
__global__ void corr_topk_kernel() {
    int bh = blockIdx.x;

    __shared__ float2 z[2048];
    __shared__ float2 tw[1024];
    __shared__ unsigned long long key[2048];
    __shared__ float sval[512];
    __shared__ int   sidx[512];
    __shared__ unsigned int hist[256];
    __shared__ int bc[2];
    __shared__ float red[256];
    __shared__ int wsum[8];

    int tid = threadIdx.x;
    int lane = tid & 31, wrp = tid >> 5;
    for (int i = tid; i < 1024; i += 256) tw[i] = g_twf[i];
    for (int i = tid; i < 2048; i += 256) {
        float2 p = g_Ps[bh * SS + i];
        z[i] = make_float2(p.x, -p.y);   // conj trick for inverse
    }
    __syncthreads();

    float2 r[8];
    fft2048_dit_hybrid(z, tw, r);
    // key[t]: value desc primary, index asc on ties (64-bit unique)
#pragma unroll
    for (int k = 0; k < 8; k++) {
        int t = tid + 256 * k;
        float v = r[k].x * (1.0f / (2048.0f * 512.0f));
        key[t] = ((unsigned long long)fenc(v) << 32) | (unsigned)(2047 - t);
    }
    __syncthreads();

    // ---- exact top-KTOP threshold via 8-round MSB radix select ----
    unsigned long long prefix = 0;
    int rem = KTOP;
    for (int round = 0; round < 8; round++) {
        int shift = 56 - 8 * round;
        hist[tid] = 0;
        __syncthreads();
        unsigned long long pmask = (round == 0) ? 0ull : (~0ull << (shift + 8));
        for (int i = tid; i < 2048; i += 256) {
            unsigned long long kv = key[i];
            if ((kv & pmask) == prefix)
                atomicAdd(&hist[(unsigned)((kv >> shift) & 255)], 1u);
        }
        __syncthreads();
        if (tid == 0) {
            unsigned int c = 0;
            int d = 255;
            for (; d > 0; d--) {
                if (c + hist[d] >= (unsigned)rem) break;
                c += hist[d];
            }
            bc[0] = d;
            bc[1] = rem - (int)c;
        }
        __syncthreads();
        prefix |= ((unsigned long long)(unsigned)bc[0]) << shift;
        rem = bc[1];
        __syncthreads();
    }
    const unsigned long long T = prefix;   // exact KTOP-th largest key

    // ---- deterministic stable compaction (index-ascending order) ----
    int base8 = tid * 8;
    int cnt = 0;
#pragma unroll
    for (int k = 0; k < 8; k++) cnt += (key[base8 + k] >= T) ? 1 : 0;
    // exclusive scan of cnt over 256 threads
    int inc = cnt;
#pragma unroll
    for (int o = 1; o < 32; o <<= 1) {
        int v = __shfl_up_sync(0xFFFFFFFFu, inc, o);
        if (lane >= o) inc += v;
    }
    if (lane == 31) wsum[wrp] = inc;
    __syncthreads();
    if (tid == 0) {
        int acc0 = 0;
#pragma unroll
        for (int w = 0; w < 8; w++) { int t = wsum[w]; wsum[w] = acc0; acc0 += t; }
    }
    __syncthreads();
    int pos = wsum[wrp] + inc - cnt;
#pragma unroll
    for (int k = 0; k < 8; k++) {
        unsigned long long kv = key[base8 + k];
        if (kv >= T) {
            sval[pos] = fdec((unsigned)(kv >> 32));
            sidx[pos] = 2047 - (int)(kv & 0xFFFFFFFFull);
            pos++;
        }
    }
    __syncthreads();

    // ---- softmax over the selected set ----
    float mx = -1e30f;
    for (int i = tid; i < KTOP; i += 256) mx = fmaxf(mx, sval[i]);
    red[tid] = mx;
    for (int off = 128; off > 0; off >>= 1) {
        __syncthreads();
        if (tid < off) red[tid] = fmaxf(red[tid], red[tid + off]);
    }
    __syncthreads();
    float maxv = red[0];
    __syncthreads();
    float ls = 0.0f;
    for (int i = tid; i < KTOP; i += 256) ls += expf(sval[i] - maxv);
    red[tid] = ls;
    for (int off = 128; off > 0; off >>= 1) {
        __syncthreads();
        if (tid < off) red[tid] += red[tid + off];
    }
    __syncthreads();
    float total = red[0];

    for (int i = tid; i < KTOP; i += 256)
        g_wk[bh * 512 + i] = make_float2(expf(sval[i] - maxv) / total, (float)sidx[i]);
}

// ---------------- kernel 3b: weighted gather ----------------
__global__ void gather_kernel(const float* __restrict__ xv) {
    int bh = blockIdx.x;
    int b  = bh >> 4;
    int tid = threadIdx.x;
    __shared__ float2 ws[KTOP];
    for (int i = tid; i < KTOP; i += 256) ws[i] = g_wk[bh * 512 + i];
    __syncthreads();

    int c = blockIdx.y * 256 + tid;
    const float* xb = xv + (size_t)b * SS * DD + c;
    float acc = 0.0f;
#pragma unroll 4
    for (int k = 0; k < KTOP; k++) {
        float2 w = ws[k];
        acc += w.x * xb[(size_t)((int)w.y) * DD];
    }
    g_zv[bh * DD + c] = acc;
}

// ---------------- kernel 3c: attend ----------------
__global__ void attend_kernel(const float* __restrict__ wv, const float* __restrict__ bv) {
    int b = blockIdx.x, jc = blockIdx.y;
    int tid = threadIdx.x;
    int j = jc * 256 + tid;
    __shared__ float zs[4][1024];
    int h0 = jc * 4;
    for (int i = tid; i < 4096; i += 256)
        zs[i >> 10][i & 1023] = g_zv[(b * HH + h0 + (i >> 10)) * DD + (i & 1023)];
    __syncthreads();

    int hl = (j >> 6) & 3;
    float acc = 0.0f;
#pragma unroll 4
    for (int c = 0; c < DD; c++)
        acc += zs[hl][c] * wv[(size_t)c * DD + j];
    g_att[b * DD + j] = acc + bv[j];
}

// ---------------- kernel 4: y[b] = attended[b] @ wo + bo ----------------
__global__ void proj_y_kernel(const float* __restrict__ wo, const float* __restrict__ bo) {
    int b = blockIdx.x;
    int j = threadIdx.x;
    __shared__ float av[DD];
    av[j] = g_att[b * DD + j];
    __syncthreads();
    float acc = 0.0f;
    for (int i = 0; i < DD; i++) acc += av[i] * wo[(size_t)i * DD + j];
    g_y[b * DD + j] = acc + bo[j];
}

// ---------------- kernel 5: broadcast across sequence ----------------
__global__ void bcast_kernel(float* __restrict__ out) {
    int idx = blockIdx.x * blockDim.x + threadIdx.x;
    int j4 = idx & 255;
    int bs = idx >> 8;
    int b  = bs >> 11;
    ((float4*)out)[idx] = ((const float4*)g_y)[b * 256 + j4];
}

// ---------------- launch ----------------
extern "C" void kernel_launch(void* const* d_in, const int* in_sizes, int n_in,
                              void* d_out, int out_size) {
    const float* xq = (const float*)d_in[0];
    const float* xk = (const float*)d_in[1];
    const float* xv = (const float*)d_in[2];
    const float* wq = (const float*)d_in[3];
    const float* bq = (const float*)d_in[4];
    const float* wk = (const float*)d_in[5];
    const float* bk = (const float*)d_in[6];
    const float* wv = (const float*)d_in[7];
    const float* bv = (const float*)d_in[8];
    const float* wo = (const float*)d_in[9];
    const float* bo = (const float*)d_in[10];
    float* out = (float*)d_out;

    __nv_bfloat16 *ahq, *alq, *ahk, *alk, *bhq, *blq, *bhk, *blk;
    cudaGetSymbolAddress((void**)&ahq, g_Ahq);
    cudaGetSymbolAddress((void**)&alq, g_Alq);
    cudaGetSymbolAddress((void**)&ahk, g_Ahk);
    cudaGetSymbolAddress((void**)&alk, g_Alk);
    cudaGetSymbolAddress((void**)&bhq, g_Bhq);
    cudaGetSymbolAddress((void**)&blq, g_Blq);
    cudaGetSymbolAddress((void**)&bhk, g_Bhk);
    cudaGetSymbolAddress((void**)&blk, g_Blk);

    cudaFuncSetAttribute(gemm_mma_kernel, cudaFuncAttributeMaxDynamicSharedMemorySize, GSMEM);

    tw_init_kernel<<<4, 256>>>();
    splitw_kernel<<<dim3(32, 32), dim3(32, 8)>>>(wq, ahq, alq);
    splitw_kernel<<<dim3(32, 32), dim3(32, 8)>>>(wk, ahk, alk);
    splitx_kernel<<<(BB * SS * DD / 4) / 256, 256>>>(xq, bhq, blq);
    splitx_kernel<<<(BB * SS * DD / 4) / 256, 256>>>(xk, bhk, blk);
    gemm_mma_kernel<<<dim3(DD / 128, SS / 256, BB * 2), 256, GSMEM>>>(bq, bk);
    fft_qk_kernel<<<BB * DD, 256>>>();
    reduce_kernel<<<dim3(BB * HH, 8), 256>>>();
    corr_topk_kernel<<<BB * HH, 256>>>();
    gather_kernel<<<dim3(BB * HH, 4), 256>>>(xv);
    attend_kernel<<<dim3(BB, 4), 256>>>(wv, bv);
    proj_y_kernel<<<BB, DD>>>(wo, bo);
    bcast_kernel<<<(BB * SS * DD / 4) / 256, 256>>>(out);
}